// round 2
// baseline (speedup 1.0000x reference)
#include <cuda_runtime.h>

// QBlock W4A8: x -> qconv1x1 -> qdw3x3 -> prelu -> qconv1x1 -> qdw3x3 -> prelu -> +x
// B=16, C=64, H=W=256, fp32 NCHW.
//
// Per-tensor fake-quant => quantized values are (int * scale). The 1x1 convs are
// computed exactly in int8(act) x int4(wt) with dp4a (int32 accum), then scaled.
// Depthwise convs run on dequantized floats (9 FFMA, memory bound).
// amax reductions are fused into each producer kernel (block reduce + atomicMax).

#define B_ 16
#define C_ 64
#define H_ 256
#define W_ 256
#define HW_ 65536
#define CHW_ 4194304           // 64*65536
#define NTOT_ 67108864         // 16*CHW
#define NPOS_ 1048576          // B*H*W

__device__ float g_buf1[NTOT_];
__device__ float g_buf2[NTOT_];
__device__ unsigned int g_amax[4];   // 0: x, 1: y1, 2: y3, 3: y4
__device__ float g_wscale[4];        // wp1, wf1, wp2, wf2
__device__ int   g_wp1[1024];        // 64 co x 16 packed int8x4 (ci)
__device__ int   g_wp2[1024];
__device__ float g_wf1[576];         // dequantized dw weights
__device__ float g_wf2[576];

__global__ void k_init() {
    if (threadIdx.x < 4) g_amax[threadIdx.x] = 0u;
}

// One block per weight tensor: amax -> scale -> quantize (+pack for 1x1)
__global__ void __launch_bounds__(256) k_wquant(const float* __restrict__ wp1,
                                                const float* __restrict__ wf1,
                                                const float* __restrict__ wp2,
                                                const float* __restrict__ wf2) {
    __shared__ float red[256];
    int tid = threadIdx.x;
    int wsel = blockIdx.x;
    const float* src = (wsel == 0) ? wp1 : (wsel == 1) ? wf1 : (wsel == 2) ? wp2 : wf2;
    int n = (wsel == 0 || wsel == 2) ? 4096 : 576;

    float m = 0.f;
    for (int i = tid; i < n; i += 256) m = fmaxf(m, fabsf(src[i]));
    red[tid] = m; __syncthreads();
    for (int s = 128; s > 0; s >>= 1) {
        if (tid < s) red[tid] = fmaxf(red[tid], red[tid + s]);
        __syncthreads();
    }
    float scale = red[0] / 7.0f + 1e-12f;
    if (tid == 0) g_wscale[wsel] = scale;

    if (wsel == 0 || wsel == 2) {
        int* dst = (wsel == 0) ? g_wp1 : g_wp2;
        for (int i = tid; i < 1024; i += 256) {
            int co = i >> 4, k = i & 15;
            unsigned int packed = 0;
            #pragma unroll
            for (int j = 0; j < 4; j++) {
                float v = src[co * 64 + k * 4 + j];
                int q = __float2int_rn(v / scale);   // exact IEEE divide (tiny tensor)
                q = max(-7, min(7, q));
                packed |= ((unsigned int)(q & 0xFF)) << (8 * j);
            }
            dst[i] = (int)packed;
        }
    } else {
        float* dst = (wsel == 1) ? g_wf1 : g_wf2;
        for (int i = tid; i < n; i += 256) {
            float q = rintf(src[i] / scale);
            q = fmaxf(-7.f, fminf(7.f, q));
            dst[i] = q * scale;   // dequantized weight value
        }
    }
}

// amax of external input x -> g_amax[0]
__global__ void __launch_bounds__(256) k_amax_x(const float4* __restrict__ in) {
    __shared__ float red[256];
    int tid = threadIdx.x;
    float m = 0.f;
    int n4 = NTOT_ / 4;
    for (int i = blockIdx.x * 256 + tid; i < n4; i += gridDim.x * 256) {
        float4 v = in[i];
        m = fmaxf(m, fmaxf(fmaxf(fabsf(v.x), fabsf(v.y)), fmaxf(fabsf(v.z), fabsf(v.w))));
    }
    red[tid] = m; __syncthreads();
    for (int s = 128; s > 0; s >>= 1) {
        if (tid < s) red[tid] = fmaxf(red[tid], red[tid + s]);
        __syncthreads();
    }
    if (tid == 0) atomicMax(&g_amax[0], __float_as_uint(red[0]));
}

// 1x1 conv, int8 x int4 dp4a, exact integer accumulation.
// in: (in_sel==0) ? ext_in : g_buf2.  out: always g_buf1.  amax(out) -> g_amax[s_out]
__global__ void __launch_bounds__(256) k_conv1x1(const float* __restrict__ ext_in,
                                                 int in_sel, int wp_sel,
                                                 int s_in, int s_w, int s_out) {
    __shared__ int ws[1024];
    __shared__ float red[256];
    int tid = threadIdx.x;
    const int* wpack = (wp_sel == 0) ? g_wp1 : g_wp2;
    for (int i = tid; i < 1024; i += 256) ws[i] = wpack[i];

    float amax_in = __uint_as_float(g_amax[s_in]);
    float scale_in = amax_in / 127.0f + 1e-12f;
    float inv_in = 1.0f / scale_in;
    float out_scale = scale_in * g_wscale[s_w];
    __syncthreads();

    const float* in = (in_sel == 0) ? ext_in : g_buf2;
    int p = blockIdx.x * 256 + tid;          // spatial position (b, hw)
    int b = p >> 16;
    int hw = p & 65535;
    const float* xin = in + (size_t)b * CHW_ + hw;

    int xq[16];
    #pragma unroll
    for (int k = 0; k < 16; k++) {
        unsigned int packed = 0;
        #pragma unroll
        for (int j = 0; j < 4; j++) {
            float v = xin[(size_t)(k * 4 + j) * HW_];
            int q = __float2int_rn(v * inv_in);
            q = max(-127, min(127, q));
            packed |= ((unsigned int)(q & 0xFF)) << (8 * j);
        }
        xq[k] = (int)packed;
    }

    float* op = g_buf1 + (size_t)b * CHW_ + hw;
    float m = 0.f;
    #pragma unroll 4
    for (int co = 0; co < 64; co++) {
        int acc = 0;
        #pragma unroll
        for (int k = 0; k < 16; k++) acc = __dp4a(xq[k], ws[co * 16 + k], acc);
        float y = (float)acc * out_scale;
        op[(size_t)co * HW_] = y;
        m = fmaxf(m, fabsf(y));
    }

    red[tid] = m; __syncthreads();
    for (int s = 128; s > 0; s >>= 1) {
        if (tid < s) red[tid] = fmaxf(red[tid], red[tid + s]);
        __syncthreads();
    }
    if (tid == 0) atomicMax(&g_amax[s_out], __float_as_uint(red[0]));
}

// Depthwise 3x3 (pad 1) + PReLU [+ residual]. Input always g_buf1.
// out: ext_out if non-null else g_buf2.  s_out >= 0 => fused amax of output.
__global__ void __launch_bounds__(256) k_dw3x3(float* __restrict__ ext_out,
                                               const float* __restrict__ resid,
                                               const float* __restrict__ alpha,
                                               int wf_sel, int s_in, int s_out) {
    __shared__ float sh[10][34];
    __shared__ float wsh[9];
    __shared__ float red[256];

    int bc = blockIdx.z;              // b*64 + c
    int c = bc & 63;
    int tx = threadIdx.x, ty = threadIdx.y;
    int tid = ty * 32 + tx;

    const float* wf = (wf_sel == 0) ? g_wf1 : g_wf2;
    if (tid < 9) wsh[tid] = wf[c * 9 + tid];

    float amax_in = __uint_as_float(g_amax[s_in]);
    float scale_in = amax_in / 127.0f + 1e-12f;
    float inv_in = 1.0f / scale_in;

    const float* plane = g_buf1 + (size_t)bc * HW_;
    int x0 = blockIdx.x * 32, y0 = blockIdx.y * 8;

    for (int i = tid; i < 340; i += 256) {
        int r = i / 34, cc = i % 34;
        int gy = y0 + r - 1, gx = x0 + cc - 1;
        float v = 0.f;
        if (gy >= 0 && gy < H_ && gx >= 0 && gx < W_) {
            float q = rintf(plane[gy * W_ + gx] * inv_in);
            q = fmaxf(-127.f, fminf(127.f, q));
            v = q * scale_in;       // dequantized activation
        }
        sh[r][cc] = v;
    }
    __syncthreads();

    float acc = 0.f;
    #pragma unroll
    for (int dy = 0; dy < 3; dy++)
        #pragma unroll
        for (int dx = 0; dx < 3; dx++)
            acc += sh[ty + dy][tx + dx] * wsh[dy * 3 + dx];

    float a = alpha[c];
    float v = (acc > 0.f) ? acc : a * acc;

    int gy = y0 + ty, gx = x0 + tx;
    size_t oidx = (size_t)bc * HW_ + (size_t)gy * W_ + gx;
    if (resid) v += resid[oidx];

    float* out = ext_out ? ext_out : g_buf2;
    out[oidx] = v;

    if (s_out >= 0) {
        red[tid] = fabsf(v); __syncthreads();
        for (int s = 128; s > 0; s >>= 1) {
            if (tid < s) red[tid] = fmaxf(red[tid], red[tid + s]);
            __syncthreads();
        }
        if (tid == 0) atomicMax(&g_amax[s_out], __float_as_uint(red[0]));
    }
}

extern "C" void kernel_launch(void* const* d_in, const int* in_sizes, int n_in,
                              void* d_out, int out_size) {
    const float* x   = (const float*)d_in[0];
    const float* wp1 = (const float*)d_in[1];
    const float* wf1 = (const float*)d_in[2];
    const float* wp2 = (const float*)d_in[3];
    const float* wf2 = (const float*)d_in[4];
    const float* a1  = (const float*)d_in[5];
    const float* a2  = (const float*)d_in[6];
    float* out = (float*)d_out;

    dim3 dwBlock(32, 8);
    dim3 dwGrid(W_ / 32, H_ / 8, B_ * C_);

    k_init<<<1, 32>>>();
    k_wquant<<<4, 256>>>(wp1, wf1, wp2, wf2);
    k_amax_x<<<8192, 256>>>((const float4*)x);

    // y1 = conv1x1(q(x), q(wp1)) -> buf1, amax -> slot1
    k_conv1x1<<<NPOS_ / 256, 256>>>(x, /*in_sel=*/0, /*wp_sel=*/0,
                                    /*s_in=*/0, /*s_w=*/0, /*s_out=*/1);
    // y3 = prelu(dw3x3(q(y1), qwf1)) -> buf2, amax -> slot2
    k_dw3x3<<<dwGrid, dwBlock>>>(nullptr, nullptr, a1, /*wf_sel=*/0,
                                 /*s_in=*/1, /*s_out=*/2);
    // y4 = conv1x1(q(y3), q(wp2)) -> buf1, amax -> slot3
    k_conv1x1<<<NPOS_ / 256, 256>>>(x, /*in_sel=*/1, /*wp_sel=*/1,
                                    /*s_in=*/2, /*s_w=*/2, /*s_out=*/3);
    // out = prelu(dw3x3(q(y4), qwf2)) + x
    k_dw3x3<<<dwGrid, dwBlock>>>(out, x, a2, /*wf_sel=*/1,
                                 /*s_in=*/3, /*s_out=*/-1);
}

// round 3
// speedup vs baseline: 2.4606x; 2.4606x over previous
#include <cuda_runtime.h>

// QBlock W4A8: x -> qconv1x1 -> qdw3x3 -> prelu -> qconv1x1 -> qdw3x3 -> prelu -> +x
// B=16, C=64, H=W=256, fp32 NCHW.

#define B_ 16
#define C_ 64
#define H_ 256
#define W_ 256
#define HW_ 65536
#define CHW_ 4194304
#define NTOT_ 67108864
#define NPOS_ 1048576

#define MAGICF 12582912.0f          // 2^23 + 2^22 : RNE integer extraction
#define MAGICI 0x4B400000

__device__ float g_buf1[NTOT_];
__device__ float g_buf2[NTOT_];
__device__ unsigned int g_amax[4];   // 0: x, 1: y1, 2: y3, 3: y4
__device__ float g_wscale[4];
__device__ int   g_wp1[1024];        // 64 co x 16 packed int8x4 (ci)
__device__ int   g_wp2[1024];
__device__ float g_wf1[576];         // dequantized dw weights
__device__ float g_wf2[576];

__device__ __forceinline__ int quant8(float v, float inv) {
    float t = fmaf(v, inv, MAGICF);
    int q = __float_as_int(t) - MAGICI;
    return max(-127, min(127, q));
}

__global__ void k_init() {
    if (threadIdx.x < 4) g_amax[threadIdx.x] = 0u;
}

__global__ void __launch_bounds__(256) k_wquant(const float* __restrict__ wp1,
                                                const float* __restrict__ wf1,
                                                const float* __restrict__ wp2,
                                                const float* __restrict__ wf2) {
    __shared__ float red[256];
    int tid = threadIdx.x;
    int wsel = blockIdx.x;
    const float* src = (wsel == 0) ? wp1 : (wsel == 1) ? wf1 : (wsel == 2) ? wp2 : wf2;
    int n = (wsel == 0 || wsel == 2) ? 4096 : 576;

    float m = 0.f;
    for (int i = tid; i < n; i += 256) m = fmaxf(m, fabsf(src[i]));
    red[tid] = m; __syncthreads();
    for (int s = 128; s > 0; s >>= 1) {
        if (tid < s) red[tid] = fmaxf(red[tid], red[tid + s]);
        __syncthreads();
    }
    float scale = red[0] / 7.0f + 1e-12f;
    if (tid == 0) g_wscale[wsel] = scale;

    if (wsel == 0 || wsel == 2) {
        int* dst = (wsel == 0) ? g_wp1 : g_wp2;
        for (int i = tid; i < 1024; i += 256) {
            int co = i >> 4, k = i & 15;
            unsigned int packed = 0;
            #pragma unroll
            for (int j = 0; j < 4; j++) {
                float v = src[co * 64 + k * 4 + j];
                int q = __float2int_rn(v / scale);
                q = max(-7, min(7, q));
                packed |= ((unsigned int)(q & 0xFF)) << (8 * j);
            }
            dst[i] = (int)packed;
        }
    } else {
        float* dst = (wsel == 1) ? g_wf1 : g_wf2;
        for (int i = tid; i < n; i += 256) {
            float q = rintf(src[i] / scale);
            q = fmaxf(-7.f, fminf(7.f, q));
            dst[i] = q * scale;
        }
    }
}

__global__ void __launch_bounds__(256) k_amax_x(const float4* __restrict__ in) {
    __shared__ unsigned int wred[8];
    int tid = threadIdx.x;
    float m = 0.f;
    int n4 = NTOT_ / 4;
    for (int i = blockIdx.x * 256 + tid; i < n4; i += gridDim.x * 256) {
        float4 v = in[i];
        m = fmaxf(m, fmaxf(fmaxf(fabsf(v.x), fabsf(v.y)), fmaxf(fabsf(v.z), fabsf(v.w))));
    }
    unsigned int u = __reduce_max_sync(0xffffffffu, __float_as_uint(m));
    if ((tid & 31) == 0) wred[tid >> 5] = u;
    __syncthreads();
    if (tid < 8) {
        unsigned int v = wred[tid];
        #pragma unroll
        for (int s = 4; s > 0; s >>= 1) v = max(v, __shfl_down_sync(0xffu, v, s));
        if (tid == 0) atomicMax(&g_amax[0], v);
    }
}

// 1x1 conv, int8 x int4 dp4a, 4 pixels per thread (float4 I/O).
__global__ void __launch_bounds__(256) k_conv1x1(const float* __restrict__ ext_in,
                                                 int in_sel, int wp_sel,
                                                 int s_in, int s_w, int s_out) {
    __shared__ int ws[1024];
    __shared__ unsigned int wred[8];
    int tid = threadIdx.x;
    const int* wpack = (wp_sel == 0) ? g_wp1 : g_wp2;
    for (int i = tid; i < 1024; i += 256) ws[i] = wpack[i];

    float amax_in = __uint_as_float(g_amax[s_in]);
    float scale_in = amax_in / 127.0f + 1e-12f;
    float inv_in = 1.0f / scale_in;
    float out_scale = scale_in * g_wscale[s_w];
    __syncthreads();

    const float* in = (in_sel == 0) ? ext_in : g_buf2;
    int p4 = blockIdx.x * 256 + tid;        // float4 index over (b,hw)
    int b = p4 >> 14;                        // 16384 float4 per plane
    int hw4 = p4 & 16383;
    const float4* in4 = (const float4*)in + (size_t)b * (CHW_ / 4) + hw4;

    int xq0[16], xq1[16], xq2[16], xq3[16];
    #pragma unroll
    for (int k = 0; k < 16; k++) {
        unsigned int p0 = 0, p1 = 0, p2 = 0, p3 = 0;
        #pragma unroll
        for (int j = 0; j < 4; j++) {
            float4 v = in4[(size_t)(k * 4 + j) * 16384];
            p0 |= ((unsigned int)(quant8(v.x, inv_in) & 0xFF)) << (8 * j);
            p1 |= ((unsigned int)(quant8(v.y, inv_in) & 0xFF)) << (8 * j);
            p2 |= ((unsigned int)(quant8(v.z, inv_in) & 0xFF)) << (8 * j);
            p3 |= ((unsigned int)(quant8(v.w, inv_in) & 0xFF)) << (8 * j);
        }
        xq0[k] = (int)p0; xq1[k] = (int)p1; xq2[k] = (int)p2; xq3[k] = (int)p3;
    }

    float4* op4 = (float4*)g_buf1 + (size_t)b * (CHW_ / 4) + hw4;
    float m = 0.f;
    #pragma unroll 2
    for (int co = 0; co < 64; co++) {
        int a0 = 0, a1 = 0, a2 = 0, a3 = 0;
        #pragma unroll
        for (int k = 0; k < 16; k++) {
            int w = ws[co * 16 + k];
            a0 = __dp4a(xq0[k], w, a0);
            a1 = __dp4a(xq1[k], w, a1);
            a2 = __dp4a(xq2[k], w, a2);
            a3 = __dp4a(xq3[k], w, a3);
        }
        float4 y;
        y.x = (float)a0 * out_scale; y.y = (float)a1 * out_scale;
        y.z = (float)a2 * out_scale; y.w = (float)a3 * out_scale;
        op4[(size_t)co * 16384] = y;
        m = fmaxf(m, fmaxf(fmaxf(fabsf(y.x), fabsf(y.y)), fmaxf(fabsf(y.z), fabsf(y.w))));
    }

    unsigned int u = __reduce_max_sync(0xffffffffu, __float_as_uint(m));
    if ((tid & 31) == 0) wred[tid >> 5] = u;
    __syncthreads();
    if (tid < 8) {
        unsigned int v = wred[tid];
        #pragma unroll
        for (int s = 4; s > 0; s >>= 1) v = max(v, __shfl_down_sync(0xffu, v, s));
        if (tid == 0) atomicMax(&g_amax[s_out], v);
    }
}

// Depthwise 3x3 (pad 1) + PReLU [+ residual]. Tile: full row (W=256) x 16 rows.
// One thread per column, register-sliding vertical window.
__global__ void __launch_bounds__(256) k_dw3x3(float* __restrict__ ext_out,
                                               const float* __restrict__ resid,
                                               const float* __restrict__ alpha,
                                               int wf_sel, int s_in, int s_out) {
    __shared__ float sh[18][258];            // col c stored at [.][c+1]; 0/257 zero
    __shared__ unsigned int wred[8];

    int bc = blockIdx.y;                      // b*64 + c
    int ch = bc & 63;
    int tid = threadIdx.x;
    int y0 = blockIdx.x * 16;

    const float* wf = (wf_sel == 0) ? g_wf1 : g_wf2;
    float w0 = wf[ch * 9 + 0], w1 = wf[ch * 9 + 1], w2 = wf[ch * 9 + 2];
    float w3 = wf[ch * 9 + 3], w4 = wf[ch * 9 + 4], w5 = wf[ch * 9 + 5];
    float w6 = wf[ch * 9 + 6], w7 = wf[ch * 9 + 7], w8 = wf[ch * 9 + 8];
    float a = alpha[ch];

    float amax_in = __uint_as_float(g_amax[s_in]);
    float scale_in = amax_in / 127.0f + 1e-12f;
    float inv_in = 1.0f / scale_in;

    const float4* plane4 = (const float4*)(g_buf1 + (size_t)bc * HW_);

    if (tid < 18) sh[tid][0] = 0.f;
    else if (tid < 36) sh[tid - 18][257] = 0.f;

    // load 18 rows x 64 float4, quantize-dequantize on the fly
    for (int i = tid; i < 18 * 64; i += 256) {
        int r = i >> 6, c4 = i & 63;
        int gy = y0 + r - 1;
        float v0 = 0.f, v1 = 0.f, v2 = 0.f, v3 = 0.f;
        if (gy >= 0 && gy < H_) {
            float4 v = plane4[gy * 64 + c4];
            v0 = (float)quant8(v.x, inv_in) * scale_in;
            v1 = (float)quant8(v.y, inv_in) * scale_in;
            v2 = (float)quant8(v.z, inv_in) * scale_in;
            v3 = (float)quant8(v.w, inv_in) * scale_in;
        }
        int c = c4 * 4 + 1;
        sh[r][c] = v0; sh[r][c + 1] = v1; sh[r][c + 2] = v2; sh[r][c + 3] = v3;
    }
    __syncthreads();

    int col = tid;                            // output column 0..255
    float t00 = sh[0][col], t01 = sh[0][col + 1], t02 = sh[0][col + 2];
    float t10 = sh[1][col], t11 = sh[1][col + 1], t12 = sh[1][col + 2];

    float* out = ext_out ? ext_out : g_buf2;
    size_t obase = (size_t)bc * HW_ + (size_t)y0 * W_ + col;
    float m = 0.f;

    #pragma unroll
    for (int r = 0; r < 16; r++) {
        float t20 = sh[r + 2][col], t21 = sh[r + 2][col + 1], t22 = sh[r + 2][col + 2];
        float acc = t00 * w0;
        acc = fmaf(t01, w1, acc); acc = fmaf(t02, w2, acc);
        acc = fmaf(t10, w3, acc); acc = fmaf(t11, w4, acc);
        acc = fmaf(t12, w5, acc); acc = fmaf(t20, w6, acc);
        acc = fmaf(t21, w7, acc); acc = fmaf(t22, w8, acc);
        float v = fmaxf(acc, 0.f) + a * fminf(acc, 0.f);   // PReLU
        size_t oidx = obase + (size_t)r * W_;
        if (resid) v += resid[oidx];
        out[oidx] = v;
        m = fmaxf(m, fabsf(v));
        t00 = t10; t01 = t11; t02 = t12;
        t10 = t20; t11 = t21; t12 = t22;
    }

    if (s_out >= 0) {
        unsigned int u = __reduce_max_sync(0xffffffffu, __float_as_uint(m));
        if ((tid & 31) == 0) wred[tid >> 5] = u;
        __syncthreads();
        if (tid < 8) {
            unsigned int v = wred[tid];
            #pragma unroll
            for (int s = 4; s > 0; s >>= 1) v = max(v, __shfl_down_sync(0xffu, v, s));
            if (tid == 0) atomicMax(&g_amax[s_out], v);
        }
    }
}

extern "C" void kernel_launch(void* const* d_in, const int* in_sizes, int n_in,
                              void* d_out, int out_size) {
    const float* x   = (const float*)d_in[0];
    const float* wp1 = (const float*)d_in[1];
    const float* wf1 = (const float*)d_in[2];
    const float* wp2 = (const float*)d_in[3];
    const float* wf2 = (const float*)d_in[4];
    const float* a1  = (const float*)d_in[5];
    const float* a2  = (const float*)d_in[6];
    float* out = (float*)d_out;

    dim3 dwGrid(H_ / 16, B_ * C_);

    k_init<<<1, 32>>>();
    k_wquant<<<4, 256>>>(wp1, wf1, wp2, wf2);
    k_amax_x<<<8192, 256>>>((const float4*)x);

    k_conv1x1<<<NPOS_ / 1024, 256>>>(x, 0, 0, /*s_in=*/0, /*s_w=*/0, /*s_out=*/1);
    k_dw3x3<<<dwGrid, 256>>>(nullptr, nullptr, a1, 0, /*s_in=*/1, /*s_out=*/2);
    k_conv1x1<<<NPOS_ / 1024, 256>>>(x, 1, 1, /*s_in=*/2, /*s_w=*/2, /*s_out=*/3);
    k_dw3x3<<<dwGrid, 256>>>(out, x, a2, 1, /*s_in=*/3, /*s_out=*/-1);
}